// round 12
// baseline (speedup 1.0000x reference)
#include <cuda_runtime.h>
#include <cuda_bf16.h>

// FM_12060268167845: factorization machine forward.
//   d_in[0] idx  i32 [B,K], d_in[1] x f32 [B,K], d_in[2] b f32 [B,K],
//   d_in[3] w f32 [1M,1], d_in[4] V f32 [1M,128], d_in[5] bias f32 [1]
// out f32 [B] = sigmoid(bias + Xw + 0.5/sum(x) * sum_f((XV)^2 - X2V2))
//
// v11: merged two-row sorted stream. Each warp owns rows {2g, 2g+1}
// (contiguous in idx), stages all 400 (off,x) pairs, ballot-bin-sorts the
// MERGED list into 8 id-range bins (64MB V slices), and runs one dense
// U=8 front-batched LDG.128 march over 400 entries (50 exact batches).
// Both rows' gathers to a given slice now happen in the same time window,
// so cross-row reuse joins within-row reuse in L2 (v10 left ~150MB of
// cross-generation refetches on the table: 614MB vs 412MB unique).
// Row attribution is carried in the sign of x (offsets stay 16B-aligned);
// two FSELs route each element into dual accumulators. Grid = 1024 CTAs
// = one resident wave, keeping chip-wide slice progression aligned.

#define FM_B 8192
#define FM_K 200
#define FM_F 128
#define WARPS 4
#define THREADS (WARPS * 32)
#define KM (2 * FM_K)              // 400 merged entries per warp
#define U 8                        // KM % U == 0 (50 batches)
#define NBIN 8
#define BIN_SHIFT 26               // 64MB slices of the 512MB V table
#define CHUNKS 13                  // ceil(400/32)

struct __align__(8) OffX { unsigned off; float x; };

__global__ __launch_bounds__(THREADS, 8)
void fm_kernel(const int* __restrict__ idx,
               const float* __restrict__ x_vals,
               const float* __restrict__ b_vals,
               const float* __restrict__ w,
               const float* __restrict__ V,
               const float* __restrict__ bias,
               float* __restrict__ out)
{
    const int warp = threadIdx.x >> 5;
    const int lane = threadIdx.x & 31;
    const unsigned lt_mask = (1u << lane) - 1u;

    __shared__ OffX  s_pairs[WARPS][KM];
    __shared__ float s_scal[WARPS][4];       // xwA, sxA, xwB, sxB

    const int gwarp = blockIdx.x * WARPS + warp;   // 0..4095
    const int bA    = gwarp * 2;                   // rows bA, bA+1
    const int baseA = bA * FM_K;                   // idx[baseA .. baseA+400)

    // ---- stage 400 merged entries in registers; fold scalars ----
    OffX e[CHUNKS];
    float xwA = 0.f, sxA = 0.f, xwB = 0.f, sxB = 0.f;
    #pragma unroll
    for (int c = 0; c < CHUNKS; ++c) {
        int g = c * 32 + lane;
        if (g < KM) {
            int   id = idx[baseA + g];
            float xv = x_vals[baseA + g];
            float bw = b_vals[baseA + g] * __ldg(&w[id]);
            bool  isB = (g >= FM_K);
            e[c].off = (unsigned)id * (FM_F * 4u);       // id * 512 bytes
            e[c].x   = isB ? -xv : xv;                   // row tag in sign
            if (isB) { sxB += xv; xwB += bw; }
            else     { sxA += xv; xwA += bw; }
        } else {
            e[c].off = 0xFFFFFFFFu;                      // sentinel: no bin
            e[c].x   = 0.0f;
        }
    }

    // Park scalars in shared (frees registers for the mainloop).
    #pragma unroll
    for (int o = 16; o > 0; o >>= 1) {
        xwA += __shfl_down_sync(0xffffffffu, xwA, o);
        sxA += __shfl_down_sync(0xffffffffu, sxA, o);
        xwB += __shfl_down_sync(0xffffffffu, xwB, o);
        sxB += __shfl_down_sync(0xffffffffu, sxB, o);
    }
    if (lane == 0) {
        s_scal[warp][0] = xwA; s_scal[warp][1] = sxA;
        s_scal[warp][2] = xwB; s_scal[warp][3] = sxB;
    }

    // ---- ballot bin-sort merged list into shared ----
    int cnt[NBIN];
    #pragma unroll
    for (int bb = 0; bb < NBIN; ++bb) cnt[bb] = 0;
    #pragma unroll
    for (int c = 0; c < CHUNKS; ++c) {
        unsigned bin = e[c].off >> BIN_SHIFT;
        #pragma unroll
        for (int bb = 0; bb < NBIN; ++bb)
            cnt[bb] += __popc(__ballot_sync(0xffffffffu, bin == (unsigned)bb));
    }
    int run[NBIN];
    {
        int acc = 0;
        #pragma unroll
        for (int bb = 0; bb < NBIN; ++bb) { run[bb] = acc; acc += cnt[bb]; }
    }
    #pragma unroll
    for (int c = 0; c < CHUNKS; ++c) {
        unsigned bin = e[c].off >> BIN_SHIFT;
        #pragma unroll
        for (int bb = 0; bb < NBIN; ++bb) {
            unsigned msk = __ballot_sync(0xffffffffu, bin == (unsigned)bb);
            if (bin == (unsigned)bb)
                s_pairs[warp][run[bb] + __popc(msk & lt_mask)] = e[c];
            run[bb] += __popc(msk);
        }
    }
    __syncwarp();

    // ---- dense U=8 mainloop over the 400-entry sorted stream ----
    const char* __restrict__ Vb = (const char*)V;
    const unsigned lane_off = (unsigned)lane << 4;
    const OffX* __restrict__ sp = s_pairs[warp];

    float4 a1A = make_float4(0.f, 0.f, 0.f, 0.f);
    float4 a1B = make_float4(0.f, 0.f, 0.f, 0.f);
    float  a2A = 0.0f, a2B = 0.0f;

    for (int k0 = 0; k0 < KM; k0 += U) {
        float4 v[U];
        float  xr[U];
        #pragma unroll
        for (int u = 0; u < U; ++u) {
            OffX ee = sp[k0 + u];
            xr[u] = ee.x;
            v[u]  = __ldg((const float4*)(Vb + ee.off + lane_off));
        }
        #pragma unroll
        for (int u = 0; u < U; ++u) {
            float xs  = xr[u];
            bool  isB = (xs < 0.0f);
            float x   = fabsf(xs);
            float xa  = isB ? 0.0f : x;
            float xb  = isB ? x : 0.0f;
            a1A.x = fmaf(xa, v[u].x, a1A.x);
            a1A.y = fmaf(xa, v[u].y, a1A.y);
            a1A.z = fmaf(xa, v[u].z, a1A.z);
            a1A.w = fmaf(xa, v[u].w, a1A.w);
            a1B.x = fmaf(xb, v[u].x, a1B.x);
            a1B.y = fmaf(xb, v[u].y, a1B.y);
            a1B.z = fmaf(xb, v[u].z, a1B.z);
            a1B.w = fmaf(xb, v[u].w, a1B.w);
            float n2 = fmaf(v[u].x, v[u].x,
                       fmaf(v[u].y, v[u].y,
                       fmaf(v[u].z, v[u].z, v[u].w * v[u].w)));
            a2A = fmaf(xa * xa, n2, a2A);
            a2B = fmaf(xb * xb, n2, a2B);
        }
    }

    // ---- reductions + outputs ----
    float pqA = fmaf(a1A.x, a1A.x,
                fmaf(a1A.y, a1A.y,
                fmaf(a1A.z, a1A.z, a1A.w * a1A.w))) - a2A;
    float pqB = fmaf(a1B.x, a1B.x,
                fmaf(a1B.y, a1B.y,
                fmaf(a1B.z, a1B.z, a1B.w * a1B.w))) - a2B;

    #pragma unroll
    for (int o = 16; o > 0; o >>= 1) {
        pqA += __shfl_down_sync(0xffffffffu, pqA, o);
        pqB += __shfl_down_sync(0xffffffffu, pqB, o);
    }

    if (lane == 0) {
        float bia = bias[0];
        float pA  = 0.5f * (1.0f / s_scal[warp][1]) * pqA;
        float lA  = bia + s_scal[warp][0] + pA;
        out[bA]   = 1.0f / (1.0f + __expf(-lA));
        float pB  = 0.5f * (1.0f / s_scal[warp][3]) * pqB;
        float lB  = bia + s_scal[warp][2] + pB;
        out[bA + 1] = 1.0f / (1.0f + __expf(-lB));
    }
}

extern "C" void kernel_launch(void* const* d_in, const int* in_sizes, int n_in,
                              void* d_out, int out_size)
{
    const int*   idx    = (const int*)d_in[0];
    const float* x_vals = (const float*)d_in[1];
    const float* b_vals = (const float*)d_in[2];
    const float* w      = (const float*)d_in[3];
    const float* V      = (const float*)d_in[4];
    const float* bias   = (const float*)d_in[5];
    float*       out    = (float*)d_out;
    (void)in_sizes; (void)n_in; (void)out_size;

    const int grid = FM_B / (WARPS * 2);   // 1024 CTAs: one resident wave
    fm_kernel<<<grid, THREADS>>>(idx, x_vals, b_vals, w, V, bias, out);
}

// round 13
// speedup vs baseline: 1.3673x; 1.3673x over previous
#include <cuda_runtime.h>
#include <cuda_bf16.h>

// FM_12060268167845: factorization machine forward.
//   d_in[0] idx  i32 [B,K], d_in[1] x f32 [B,K], d_in[2] b f32 [B,K],
//   d_in[3] w f32 [1M,1], d_in[4] V f32 [1M,128], d_in[5] bias f32 [1]
// out f32 [B] = sigmoid(bias + Xw + 0.5/sum(x) * sum_f((XV)^2 - X2V2))
//
// v12: dual per-row sorted streams, batch-interleaved.
// Each warp owns rows {2g, 2g+1}; each row's 200 (off,x) pairs are
// ballot-bin-sorted SEPARATELY (v10's sort). The mainloop alternates U=8
// dense batches: A[k0..k0+8) -> accums A, B[k0..k0+8) -> accums B. Both
// streams march bins at the same rate, so cross-row reuse lands in the
// same L2 window (v11 measured 552MB traffic) while each batch keeps
// v10's untouched 8-FMA/element loop -- no tags, no selects, no doubled
// FLOPs (v11's fatal flaw: issue 58%). v/xr buffers are time-shared
// between A and B batches; xw/sx parked in shared. Grid = 1024 CTAs
// = one resident wave.

#define FM_B 8192
#define FM_K 200
#define FM_F 128
#define WARPS 4
#define THREADS (WARPS * 32)
#define U 8                        // FM_K % U == 0 (25 batches per row)
#define NBIN 8
#define BIN_SHIFT 26               // 64MB slices of the 512MB V table
#define CHUNKS 7                   // ceil(200/32)

struct __align__(8) OffX { unsigned off; float x; };

__global__ __launch_bounds__(THREADS, 8)
void fm_kernel(const int* __restrict__ idx,
               const float* __restrict__ x_vals,
               const float* __restrict__ b_vals,
               const float* __restrict__ w,
               const float* __restrict__ V,
               const float* __restrict__ bias,
               float* __restrict__ out)
{
    const int warp = threadIdx.x >> 5;
    const int lane = threadIdx.x & 31;
    const unsigned lt_mask = (1u << lane) - 1u;

    __shared__ OffX  s_pairs[WARPS][2][FM_K];
    __shared__ float s_scal[WARPS][4];        // xwA, sxA, xwB, sxB

    const int gwarp = blockIdx.x * WARPS + warp;   // 0..4095
    const int bA    = gwarp * 2;                   // rows bA, bA+1

    // ---- per-row: stage + ballot bin-sort (v10's proven sort) ----
    for (int r = 0; r < 2; ++r) {
        const int base = (bA + r) * FM_K;

        OffX e[CHUNKS];
        float xw = 0.0f, sx = 0.0f;
        #pragma unroll
        for (int c = 0; c < CHUNKS; ++c) {
            int k = c * 32 + lane;
            if (k < FM_K) {
                int   id = idx[base + k];
                float xv = x_vals[base + k];
                e[c].off = (unsigned)id * (FM_F * 4u);   // id * 512 bytes
                e[c].x   = xv;
                sx += xv;
                xw = fmaf(b_vals[base + k], __ldg(&w[id]), xw);
            } else {
                e[c].off = 0xFFFFFFFFu;                  // sentinel: no bin
                e[c].x   = 0.0f;
            }
        }

        #pragma unroll
        for (int o = 16; o > 0; o >>= 1) {
            xw += __shfl_down_sync(0xffffffffu, xw, o);
            sx += __shfl_down_sync(0xffffffffu, sx, o);
        }
        if (lane == 0) {
            s_scal[warp][2 * r + 0] = xw;
            s_scal[warp][2 * r + 1] = sx;
        }

        int cnt[NBIN];
        #pragma unroll
        for (int bb = 0; bb < NBIN; ++bb) cnt[bb] = 0;
        #pragma unroll
        for (int c = 0; c < CHUNKS; ++c) {
            unsigned bin = e[c].off >> BIN_SHIFT;
            #pragma unroll
            for (int bb = 0; bb < NBIN; ++bb)
                cnt[bb] += __popc(__ballot_sync(0xffffffffu, bin == (unsigned)bb));
        }
        int run[NBIN];
        {
            int acc = 0;
            #pragma unroll
            for (int bb = 0; bb < NBIN; ++bb) { run[bb] = acc; acc += cnt[bb]; }
        }
        #pragma unroll
        for (int c = 0; c < CHUNKS; ++c) {
            unsigned bin = e[c].off >> BIN_SHIFT;
            #pragma unroll
            for (int bb = 0; bb < NBIN; ++bb) {
                unsigned msk = __ballot_sync(0xffffffffu, bin == (unsigned)bb);
                if (bin == (unsigned)bb)
                    s_pairs[warp][r][run[bb] + __popc(msk & lt_mask)] = e[c];
                run[bb] += __popc(msk);
            }
        }
    }
    __syncwarp();

    // ---- batch-interleaved dense mainloop (A batch, then B batch) ----
    const char* __restrict__ Vb = (const char*)V;
    const unsigned lane_off = (unsigned)lane << 4;
    const OffX* __restrict__ spA = s_pairs[warp][0];
    const OffX* __restrict__ spB = s_pairs[warp][1];

    float4 a1A = make_float4(0.f, 0.f, 0.f, 0.f);
    float4 a1B = make_float4(0.f, 0.f, 0.f, 0.f);
    float  a2A = 0.0f, a2B = 0.0f;

    for (int k0 = 0; k0 < FM_K; k0 += U) {
        {   // --- row A batch ---
            float4 v[U];
            float  xr[U];
            #pragma unroll
            for (int u = 0; u < U; ++u) {
                OffX ee = spA[k0 + u];
                xr[u] = ee.x;
                v[u]  = __ldg((const float4*)(Vb + ee.off + lane_off));
            }
            #pragma unroll
            for (int u = 0; u < U; ++u) {
                float x  = xr[u];
                float x2 = x * x;
                a1A.x = fmaf(x, v[u].x, a1A.x);
                a1A.y = fmaf(x, v[u].y, a1A.y);
                a1A.z = fmaf(x, v[u].z, a1A.z);
                a1A.w = fmaf(x, v[u].w, a1A.w);
                float n2 = fmaf(v[u].x, v[u].x,
                           fmaf(v[u].y, v[u].y,
                           fmaf(v[u].z, v[u].z, v[u].w * v[u].w)));
                a2A = fmaf(x2, n2, a2A);
            }
        }
        {   // --- row B batch ---
            float4 v[U];
            float  xr[U];
            #pragma unroll
            for (int u = 0; u < U; ++u) {
                OffX ee = spB[k0 + u];
                xr[u] = ee.x;
                v[u]  = __ldg((const float4*)(Vb + ee.off + lane_off));
            }
            #pragma unroll
            for (int u = 0; u < U; ++u) {
                float x  = xr[u];
                float x2 = x * x;
                a1B.x = fmaf(x, v[u].x, a1B.x);
                a1B.y = fmaf(x, v[u].y, a1B.y);
                a1B.z = fmaf(x, v[u].z, a1B.z);
                a1B.w = fmaf(x, v[u].w, a1B.w);
                float n2 = fmaf(v[u].x, v[u].x,
                           fmaf(v[u].y, v[u].y,
                           fmaf(v[u].z, v[u].z, v[u].w * v[u].w)));
                a2B = fmaf(x2, n2, a2B);
            }
        }
    }

    // ---- reductions + outputs ----
    float pqA = fmaf(a1A.x, a1A.x,
                fmaf(a1A.y, a1A.y,
                fmaf(a1A.z, a1A.z, a1A.w * a1A.w))) - a2A;
    float pqB = fmaf(a1B.x, a1B.x,
                fmaf(a1B.y, a1B.y,
                fmaf(a1B.z, a1B.z, a1B.w * a1B.w))) - a2B;

    #pragma unroll
    for (int o = 16; o > 0; o >>= 1) {
        pqA += __shfl_down_sync(0xffffffffu, pqA, o);
        pqB += __shfl_down_sync(0xffffffffu, pqB, o);
    }

    if (lane == 0) {
        float bia = bias[0];
        float pA  = 0.5f * (1.0f / s_scal[warp][1]) * pqA;
        out[bA]     = 1.0f / (1.0f + __expf(-(bia + s_scal[warp][0] + pA)));
        float pB  = 0.5f * (1.0f / s_scal[warp][3]) * pqB;
        out[bA + 1] = 1.0f / (1.0f + __expf(-(bia + s_scal[warp][2] + pB)));
    }
}

extern "C" void kernel_launch(void* const* d_in, const int* in_sizes, int n_in,
                              void* d_out, int out_size)
{
    const int*   idx    = (const int*)d_in[0];
    const float* x_vals = (const float*)d_in[1];
    const float* b_vals = (const float*)d_in[2];
    const float* w      = (const float*)d_in[3];
    const float* V      = (const float*)d_in[4];
    const float* bias   = (const float*)d_in[5];
    float*       out    = (float*)d_out;
    (void)in_sizes; (void)n_in; (void)out_size;

    const int grid = FM_B / (WARPS * 2);   // 1024 CTAs: one resident wave
    fm_kernel<<<grid, THREADS>>>(idx, x_vals, b_vals, w, V, bias, out);
}

// round 14
// speedup vs baseline: 1.3975x; 1.0221x over previous
#include <cuda_runtime.h>
#include <cuda_bf16.h>

// FM_12060268167845: factorization machine forward.
//   d_in[0] idx  i32 [B,K], d_in[1] x f32 [B,K], d_in[2] b f32 [B,K],
//   d_in[3] w f32 [1M,1], d_in[4] V f32 [1M,128], d_in[5] bias f32 [1]
// out f32 [B] = sigmoid(bias + Xw + 0.5/sum(x) * sum_f((XV)^2 - X2V2))
//
// v13 = v12 (dual per-row sorted streams, batch-interleaved; traffic at
// the ~451MB compulsory floor) with deeper per-warp MLP to refill the
// DRAM-miss queue (only ~46% of gathers miss now, so queue depth halved
// vs the pure-random kernel; warp count is fixed at 4096 by rows/2):
//   - U = 10 loads per batch (was 8)
//   - offsets and x split into separate smem arrays; x read from shared
//     in the consume loop (frees the xr[] register buffer to afford U=10)
//   - __ldcg on V (no L1 reuse; frees l1tex wavefronts for LDS traffic)

#define FM_B 8192
#define FM_K 200
#define FM_F 128
#define WARPS 4
#define THREADS (WARPS * 32)
#define U 10                       // FM_K % U == 0 (20 batches per row)
#define NBIN 8
#define BIN_SHIFT 26               // 64MB slices of the 512MB V table
#define CHUNKS 7                   // ceil(200/32)

__global__ __launch_bounds__(THREADS, 8)
void fm_kernel(const int* __restrict__ idx,
               const float* __restrict__ x_vals,
               const float* __restrict__ b_vals,
               const float* __restrict__ w,
               const float* __restrict__ V,
               const float* __restrict__ bias,
               float* __restrict__ out)
{
    const int warp = threadIdx.x >> 5;
    const int lane = threadIdx.x & 31;
    const unsigned lt_mask = (1u << lane) - 1u;

    __shared__ unsigned s_off[WARPS][2][FM_K];
    __shared__ float    s_x[WARPS][2][FM_K];
    __shared__ float    s_scal[WARPS][4];     // xwA, sxA, xwB, sxB

    const int gwarp = blockIdx.x * WARPS + warp;   // 0..4095
    const int bA    = gwarp * 2;                   // rows bA, bA+1

    // ---- per-row: stage + ballot bin-sort ----
    for (int r = 0; r < 2; ++r) {
        const int base = (bA + r) * FM_K;

        unsigned eoff[CHUNKS];
        float    ex[CHUNKS];
        float xw = 0.0f, sx = 0.0f;
        #pragma unroll
        for (int c = 0; c < CHUNKS; ++c) {
            int k = c * 32 + lane;
            if (k < FM_K) {
                int   id = idx[base + k];
                float xv = x_vals[base + k];
                eoff[c] = (unsigned)id * (FM_F * 4u);    // id * 512 bytes
                ex[c]   = xv;
                sx += xv;
                xw = fmaf(b_vals[base + k], __ldg(&w[id]), xw);
            } else {
                eoff[c] = 0xFFFFFFFFu;                   // sentinel: no bin
                ex[c]   = 0.0f;
            }
        }

        #pragma unroll
        for (int o = 16; o > 0; o >>= 1) {
            xw += __shfl_down_sync(0xffffffffu, xw, o);
            sx += __shfl_down_sync(0xffffffffu, sx, o);
        }
        if (lane == 0) {
            s_scal[warp][2 * r + 0] = xw;
            s_scal[warp][2 * r + 1] = sx;
        }

        int cnt[NBIN];
        #pragma unroll
        for (int bb = 0; bb < NBIN; ++bb) cnt[bb] = 0;
        #pragma unroll
        for (int c = 0; c < CHUNKS; ++c) {
            unsigned bin = eoff[c] >> BIN_SHIFT;
            #pragma unroll
            for (int bb = 0; bb < NBIN; ++bb)
                cnt[bb] += __popc(__ballot_sync(0xffffffffu, bin == (unsigned)bb));
        }
        int run[NBIN];
        {
            int acc = 0;
            #pragma unroll
            for (int bb = 0; bb < NBIN; ++bb) { run[bb] = acc; acc += cnt[bb]; }
        }
        #pragma unroll
        for (int c = 0; c < CHUNKS; ++c) {
            unsigned bin = eoff[c] >> BIN_SHIFT;
            #pragma unroll
            for (int bb = 0; bb < NBIN; ++bb) {
                unsigned msk = __ballot_sync(0xffffffffu, bin == (unsigned)bb);
                if (bin == (unsigned)bb) {
                    int pos = run[bb] + __popc(msk & lt_mask);
                    s_off[warp][r][pos] = eoff[c];
                    s_x[warp][r][pos]   = ex[c];
                }
                run[bb] += __popc(msk);
            }
        }
    }
    __syncwarp();

    // ---- batch-interleaved dense mainloop (A batch, then B batch) ----
    const char* __restrict__ Vb = (const char*)V;
    const unsigned lane_off = (unsigned)lane << 4;
    const unsigned* __restrict__ offA = s_off[warp][0];
    const unsigned* __restrict__ offB = s_off[warp][1];
    const float*    __restrict__ xA   = s_x[warp][0];
    const float*    __restrict__ xB   = s_x[warp][1];

    float4 a1A = make_float4(0.f, 0.f, 0.f, 0.f);
    float4 a1B = make_float4(0.f, 0.f, 0.f, 0.f);
    float  a2A = 0.0f, a2B = 0.0f;

    for (int k0 = 0; k0 < FM_K; k0 += U) {
        {   // --- row A batch ---
            float4 v[U];
            #pragma unroll
            for (int u = 0; u < U; ++u)
                v[u] = __ldcg((const float4*)(Vb + offA[k0 + u] + lane_off));
            #pragma unroll
            for (int u = 0; u < U; ++u) {
                float x  = xA[k0 + u];
                float x2 = x * x;
                a1A.x = fmaf(x, v[u].x, a1A.x);
                a1A.y = fmaf(x, v[u].y, a1A.y);
                a1A.z = fmaf(x, v[u].z, a1A.z);
                a1A.w = fmaf(x, v[u].w, a1A.w);
                float n2 = fmaf(v[u].x, v[u].x,
                           fmaf(v[u].y, v[u].y,
                           fmaf(v[u].z, v[u].z, v[u].w * v[u].w)));
                a2A = fmaf(x2, n2, a2A);
            }
        }
        {   // --- row B batch ---
            float4 v[U];
            #pragma unroll
            for (int u = 0; u < U; ++u)
                v[u] = __ldcg((const float4*)(Vb + offB[k0 + u] + lane_off));
            #pragma unroll
            for (int u = 0; u < U; ++u) {
                float x  = xB[k0 + u];
                float x2 = x * x;
                a1B.x = fmaf(x, v[u].x, a1B.x);
                a1B.y = fmaf(x, v[u].y, a1B.y);
                a1B.z = fmaf(x, v[u].z, a1B.z);
                a1B.w = fmaf(x, v[u].w, a1B.w);
                float n2 = fmaf(v[u].x, v[u].x,
                           fmaf(v[u].y, v[u].y,
                           fmaf(v[u].z, v[u].z, v[u].w * v[u].w)));
                a2B = fmaf(x2, n2, a2B);
            }
        }
    }

    // ---- reductions + outputs ----
    float pqA = fmaf(a1A.x, a1A.x,
                fmaf(a1A.y, a1A.y,
                fmaf(a1A.z, a1A.z, a1A.w * a1A.w))) - a2A;
    float pqB = fmaf(a1B.x, a1B.x,
                fmaf(a1B.y, a1B.y,
                fmaf(a1B.z, a1B.z, a1B.w * a1B.w))) - a2B;

    #pragma unroll
    for (int o = 16; o > 0; o >>= 1) {
        pqA += __shfl_down_sync(0xffffffffu, pqA, o);
        pqB += __shfl_down_sync(0xffffffffu, pqB, o);
    }

    if (lane == 0) {
        float bia = bias[0];
        float pA  = 0.5f * (1.0f / s_scal[warp][1]) * pqA;
        out[bA]     = 1.0f / (1.0f + __expf(-(bia + s_scal[warp][0] + pA)));
        float pB  = 0.5f * (1.0f / s_scal[warp][3]) * pqB;
        out[bA + 1] = 1.0f / (1.0f + __expf(-(bia + s_scal[warp][2] + pB)));
    }
}

extern "C" void kernel_launch(void* const* d_in, const int* in_sizes, int n_in,
                              void* d_out, int out_size)
{
    const int*   idx    = (const int*)d_in[0];
    const float* x_vals = (const float*)d_in[1];
    const float* b_vals = (const float*)d_in[2];
    const float* w      = (const float*)d_in[3];
    const float* V      = (const float*)d_in[4];
    const float* bias   = (const float*)d_in[5];
    float*       out    = (float*)d_out;
    (void)in_sizes; (void)n_in; (void)out_size;

    const int grid = FM_B / (WARPS * 2);   // 1024 CTAs: one resident wave
    fm_kernel<<<grid, THREADS>>>(idx, x_vals, b_vals, w, V, bias, out);
}